// round 1
// baseline (speedup 1.0000x reference)
#include <cuda_runtime.h>
#include <stdint.h>

// Problem constants (match reference)
#define N_ELEMS   4194304      // total elements
#define NUM_IDS   262144
#define M_CAP     (NUM_IDS + 1)  // 262145 output rows
#define L_CAP     128

// Scan decomposition: 1024 blocks * 4096 elems; 256 threads * 16 items/thread
#define NB        1024
#define EPB       4096
#define BLK       256
#define IPT       16

// Scratch (device globals: no allocation allowed)
__device__ int g_start_idx[M_CAP];   // start element index of run s
__device__ int g_block_cnt[NB];
__device__ int g_block_pfx[NB];      // exclusive prefix of block counts
__device__ int g_num_runs;

// ---------------------------------------------------------------------------
// Kernel 1: count run-starts per block. A start is i==0 or ids[i]!=ids[i-1].
// ---------------------------------------------------------------------------
__global__ __launch_bounds__(BLK) void k_count(const int* __restrict__ ids) {
    const int b  = blockIdx.x;
    const int t  = threadIdx.x;
    const int i0 = b * EPB + t * IPT;

    const int4* p = reinterpret_cast<const int4*>(ids + i0);
    int4 a0 = p[0], a1 = p[1], a2 = p[2], a3 = p[3];
    int v[IPT] = {a0.x, a0.y, a0.z, a0.w,
                  a1.x, a1.y, a1.z, a1.w,
                  a2.x, a2.y, a2.z, a2.w,
                  a3.x, a3.y, a3.z, a3.w};

    int prev = (i0 == 0) ? ~v[0] : ids[i0 - 1];
    int cnt = 0;
#pragma unroll
    for (int j = 0; j < IPT; j++) {
        cnt += (v[j] != prev);
        prev = v[j];
    }

    // block reduce
    __shared__ int sh[BLK / 32];
#pragma unroll
    for (int off = 16; off > 0; off >>= 1)
        cnt += __shfl_down_sync(0xFFFFFFFFu, cnt, off);
    if ((t & 31) == 0) sh[t >> 5] = cnt;
    __syncthreads();
    if (t < BLK / 32) {
        int s = sh[t];
#pragma unroll
        for (int off = (BLK / 64); off > 0; off >>= 1)
            s += __shfl_down_sync(0xFFu, s, off);
        if (t == 0) g_block_cnt[b] = s;
    }
}

// ---------------------------------------------------------------------------
// Kernel 2: single-block exclusive scan of the NB block counts.
// ---------------------------------------------------------------------------
__global__ __launch_bounds__(NB) void k_scan() {
    __shared__ int sh[NB];
    const int t = threadIdx.x;
    int v = g_block_cnt[t];
    sh[t] = v;
    __syncthreads();
#pragma unroll
    for (int off = 1; off < NB; off <<= 1) {
        int x = (t >= off) ? sh[t - off] : 0;
        __syncthreads();
        sh[t] += x;
        __syncthreads();
    }
    g_block_pfx[t] = sh[t] - v;   // exclusive
    if (t == NB - 1) g_num_runs = sh[t];
}

// ---------------------------------------------------------------------------
// Kernel 3: recompute starts, block-local exclusive scan, scatter start_idx.
// ---------------------------------------------------------------------------
__global__ __launch_bounds__(BLK) void k_starts(const int* __restrict__ ids) {
    const int b  = blockIdx.x;
    const int t  = threadIdx.x;
    const int i0 = b * EPB + t * IPT;

    const int4* p = reinterpret_cast<const int4*>(ids + i0);
    int4 a0 = p[0], a1 = p[1], a2 = p[2], a3 = p[3];
    int v[IPT] = {a0.x, a0.y, a0.z, a0.w,
                  a1.x, a1.y, a1.z, a1.w,
                  a2.x, a2.y, a2.z, a2.w,
                  a3.x, a3.y, a3.z, a3.w};

    int first_prev = (i0 == 0) ? ~v[0] : ids[i0 - 1];

    // per-thread count
    int prev = first_prev;
    int cnt = 0;
#pragma unroll
    for (int j = 0; j < IPT; j++) {
        cnt += (v[j] != prev);
        prev = v[j];
    }

    // block-wide exclusive scan of per-thread counts (Hillis-Steele in smem)
    __shared__ int sh[BLK];
    sh[t] = cnt;
    __syncthreads();
#pragma unroll
    for (int off = 1; off < BLK; off <<= 1) {
        int x = (t >= off) ? sh[t - off] : 0;
        __syncthreads();
        sh[t] += x;
        __syncthreads();
    }
    int rank = g_block_pfx[b] + (sh[t] - cnt);

    // scatter start indices in element order
    prev = first_prev;
#pragma unroll
    for (int j = 0; j < IPT; j++) {
        if (v[j] != prev) {
            g_start_idx[rank] = i0 + j;
            rank++;
        }
        prev = v[j];
    }
}

// ---------------------------------------------------------------------------
// Kernel 4: fill output. Row s of padded + run_ids[s].
// Output layout (float32): [0, M_CAP) = run_ids, then padded row-major.
// ---------------------------------------------------------------------------
__global__ __launch_bounds__(L_CAP) void k_fill(const int* __restrict__ ids,
                                                const float* __restrict__ feats,
                                                float* __restrict__ out) {
    const int s = blockIdx.x;     // 0 .. M_CAP-1
    const int t = threadIdx.x;    // 0 .. 127
    float* row = out + M_CAP + (size_t)s * L_CAP;

    const int nr = g_num_runs;
    if (s < nr - 1) {
        const int start = g_start_idx[s];
        const int end   = g_start_idx[s + 1];
        const int len   = end - start;
        if (t == 0) out[s] = (float)ids[start];
        row[t] = (t < len) ? feats[start + t] : 0.0f;
    } else {
        if (t == 0) out[s] = -1.0f;
        row[t] = 0.0f;
    }
}

// ---------------------------------------------------------------------------
extern "C" void kernel_launch(void* const* d_in, const int* in_sizes, int n_in,
                              void* d_out, int out_size) {
    const int*   ids   = (const int*)d_in[0];
    const float* feats = (const float*)d_in[1];
    float*       out   = (float*)d_out;

    k_count <<<NB, BLK>>>(ids);
    k_scan  <<<1, NB>>>();
    k_starts<<<NB, BLK>>>(ids);
    k_fill  <<<M_CAP, L_CAP>>>(ids, feats, out);
}

// round 2
// speedup vs baseline: 2.3153x; 2.3153x over previous
#include <cuda_runtime.h>
#include <stdint.h>

// Problem constants (match reference)
#define N_ELEMS   4194304        // total elements
#define NUM_IDS   262144
#define M_CAP     (NUM_IDS + 1)  // 262145 output rows
#define L_CAP     128
#define OUT_TOTAL (M_CAP + M_CAP * L_CAP)   // 33,816,705 floats
#define NCHUNKS   (OUT_TOTAL / 4)           // 8,454,176 aligned float4 + 1 tail

// Scan decomposition: 1024 blocks * 4096 elems; 256 threads * 16 items/thread
#define NB        1024
#define EPB       4096
#define BLK       256
#define IPT       16

// Scratch (device globals: no allocation allowed)
__device__ int2 g_runs[M_CAP];   // {start element index, id value} of run s
__device__ int  g_block_cnt[NB];
__device__ int  g_block_pfx[NB]; // exclusive prefix of block counts
__device__ int  g_num_runs;

// ---------------------------------------------------------------------------
// Kernel 1: count run-starts per block. A start is i==0 or ids[i]!=ids[i-1].
// ---------------------------------------------------------------------------
__global__ __launch_bounds__(BLK) void k_count(const int* __restrict__ ids) {
    const int b  = blockIdx.x;
    const int t  = threadIdx.x;
    const int i0 = b * EPB + t * IPT;

    const int4* p = reinterpret_cast<const int4*>(ids + i0);
    int4 a0 = p[0], a1 = p[1], a2 = p[2], a3 = p[3];
    int v[IPT] = {a0.x, a0.y, a0.z, a0.w,
                  a1.x, a1.y, a1.z, a1.w,
                  a2.x, a2.y, a2.z, a2.w,
                  a3.x, a3.y, a3.z, a3.w};

    int prev = (i0 == 0) ? ~v[0] : ids[i0 - 1];
    int cnt = 0;
#pragma unroll
    for (int j = 0; j < IPT; j++) {
        cnt += (v[j] != prev);
        prev = v[j];
    }

    __shared__ int sh[BLK / 32];
#pragma unroll
    for (int off = 16; off > 0; off >>= 1)
        cnt += __shfl_down_sync(0xFFFFFFFFu, cnt, off);
    if ((t & 31) == 0) sh[t >> 5] = cnt;
    __syncthreads();
    if (t < BLK / 32) {
        int s = sh[t];
#pragma unroll
        for (int off = (BLK / 64); off > 0; off >>= 1)
            s += __shfl_down_sync(0xFFu, s, off);
        if (t == 0) g_block_cnt[b] = s;
    }
}

// ---------------------------------------------------------------------------
// Kernel 2: single-block exclusive scan of the NB block counts.
// ---------------------------------------------------------------------------
__global__ __launch_bounds__(NB) void k_scan() {
    __shared__ int sh[NB];
    const int t = threadIdx.x;
    int v = g_block_cnt[t];
    sh[t] = v;
    __syncthreads();
#pragma unroll
    for (int off = 1; off < NB; off <<= 1) {
        int x = (t >= off) ? sh[t - off] : 0;
        __syncthreads();
        sh[t] += x;
        __syncthreads();
    }
    g_block_pfx[t] = sh[t] - v;   // exclusive
    if (t == NB - 1) g_num_runs = sh[t];
}

// ---------------------------------------------------------------------------
// Kernel 3: recompute starts, block-local exclusive scan, scatter (start,id).
// ---------------------------------------------------------------------------
__global__ __launch_bounds__(BLK) void k_starts(const int* __restrict__ ids) {
    const int b  = blockIdx.x;
    const int t  = threadIdx.x;
    const int i0 = b * EPB + t * IPT;

    const int4* p = reinterpret_cast<const int4*>(ids + i0);
    int4 a0 = p[0], a1 = p[1], a2 = p[2], a3 = p[3];
    int v[IPT] = {a0.x, a0.y, a0.z, a0.w,
                  a1.x, a1.y, a1.z, a1.w,
                  a2.x, a2.y, a2.z, a2.w,
                  a3.x, a3.y, a3.z, a3.w};

    int first_prev = (i0 == 0) ? ~v[0] : ids[i0 - 1];

    int prev = first_prev;
    int cnt = 0;
#pragma unroll
    for (int j = 0; j < IPT; j++) {
        cnt += (v[j] != prev);
        prev = v[j];
    }

    __shared__ int sh[BLK];
    sh[t] = cnt;
    __syncthreads();
#pragma unroll
    for (int off = 1; off < BLK; off <<= 1) {
        int x = (t >= off) ? sh[t - off] : 0;
        __syncthreads();
        sh[t] += x;
        __syncthreads();
    }
    int rank = g_block_pfx[b] + (sh[t] - cnt);

    prev = first_prev;
#pragma unroll
    for (int j = 0; j < IPT; j++) {
        if (v[j] != prev) {
            g_runs[rank] = make_int2(i0 + j, v[j]);
            rank++;
        }
        prev = v[j];
    }
}

// ---------------------------------------------------------------------------
// Kernel 4: fill ENTIRE output with aligned float4 stores.
// Flat layout (float32): out[0..M_CAP) = run_ids, then padded [M_CAP x 128].
// Chunk i covers float indices [4i, 4i+4). Padded element at flat index
// a >= M_CAP maps to g = a - M_CAP, row s = g>>7, col c = g&127.
// Since M_CAP % 4 == 1 and 128 % 4 == 0, every aligned chunk in the padded
// region has cols {3+4m..6+4m} of one row, except the 1-per-row straddle
// chunk (cols 127 | 0,1,2 of next row) and the single region-boundary chunk.
// ---------------------------------------------------------------------------
#define FB 256
__global__ __launch_bounds__(FB) void k_fill(const float* __restrict__ feats,
                                             float* __restrict__ out) {
    const unsigned i = blockIdx.x * FB + threadIdx.x;
    if (i > NCHUNKS) return;
    if (i == NCHUNKS) {            // single tail float (col 127 of last row)
        out[OUT_TOTAL - 1] = 0.0f;
        return;
    }
    const int nr1 = g_num_runs - 1;
    const int a0  = (int)(4u * i);
    float4 v;

    if (a0 + 3 < M_CAP) {
        // ---- run_ids region ----
        v.x = (a0     < nr1) ? (float)g_runs[a0    ].y : -1.0f;
        v.y = (a0 + 1 < nr1) ? (float)g_runs[a0 + 1].y : -1.0f;
        v.z = (a0 + 2 < nr1) ? (float)g_runs[a0 + 2].y : -1.0f;
        v.w = (a0 + 3 < nr1) ? (float)g_runs[a0 + 3].y : -1.0f;
    } else if (a0 >= M_CAP + 3) {
        // ---- padded region ----
        const int g0 = a0 - M_CAP;
        const int sA = g0 >> 7;
        const int sB = (g0 + 3) >> 7;
        if (sA == sB) {
            const int c = g0 & 127;
            int startA = 0, lenA = 0;
            const bool vA = (sA < nr1);
            if (vA) {
                int2 rA = g_runs[sA];
                startA  = rA.x;
                lenA    = g_runs[sA + 1].x - startA;
            }
            v.x = (vA && c     < lenA) ? feats[startA + c    ] : 0.0f;
            v.y = (vA && c + 1 < lenA) ? feats[startA + c + 1] : 0.0f;
            v.z = (vA && c + 2 < lenA) ? feats[startA + c + 2] : 0.0f;
            v.w = (vA && c + 3 < lenA) ? feats[startA + c + 3] : 0.0f;
        } else {
            // straddles a row boundary: generic per-element (1 lane per warp)
            float t[4];
#pragma unroll
            for (int k = 0; k < 4; k++) {
                const int g = g0 + k;
                const int s = g >> 7, c = g & 127;
                float x = 0.0f;
                if (s < nr1) {
                    const int st = g_runs[s].x;
                    const int ln = g_runs[s + 1].x - st;
                    if (c < ln) x = feats[st + c];
                }
                t[k] = x;
            }
            v = make_float4(t[0], t[1], t[2], t[3]);
        }
    } else {
        // ---- the single region-boundary chunk: a0 == M_CAP - 1 ----
        // element 0: run_ids[M_CAP-1]; elements 1..3: row 0, cols 0..2
        v.x = (M_CAP - 1 < nr1) ? (float)g_runs[M_CAP - 1].y : -1.0f;
        int st = 0, ln = 0;
        const bool v0 = (0 < nr1);
        if (v0) {
            st = g_runs[0].x;
            ln = g_runs[1].x - st;
        }
        v.y = (v0 && 0 < ln) ? feats[st + 0] : 0.0f;
        v.z = (v0 && 1 < ln) ? feats[st + 1] : 0.0f;
        v.w = (v0 && 2 < ln) ? feats[st + 2] : 0.0f;
    }

    reinterpret_cast<float4*>(out)[i] = v;
}

// ---------------------------------------------------------------------------
extern "C" void kernel_launch(void* const* d_in, const int* in_sizes, int n_in,
                              void* d_out, int out_size) {
    const int*   ids   = (const int*)d_in[0];
    const float* feats = (const float*)d_in[1];
    float*       out   = (float*)d_out;

    k_count <<<NB, BLK>>>(ids);
    k_scan  <<<1, NB>>>();
    k_starts<<<NB, BLK>>>(ids);

    const int fill_blocks = (NCHUNKS + 1 + FB - 1) / FB;
    k_fill  <<<fill_blocks, FB>>>(feats, out);
}

// round 3
// speedup vs baseline: 3.3361x; 1.4409x over previous
#include <cuda_runtime.h>
#include <stdint.h>

// Problem constants (match reference)
#define N_ELEMS   4194304        // total elements
#define NUM_IDS   262144
#define M_CAP     (NUM_IDS + 1)  // 262145 output rows
#define L_CAP     128
#define OUT_TOTAL (M_CAP + M_CAP * L_CAP)   // 33,816,705 floats
#define NW        264193         // full 128-float windows (NW*128 = OUT_TOTAL-1)

// Scan decomposition: 1024 blocks * 4096 elems; 256 threads * 16 items/thread
#define NB        1024
#define EPB       4096
#define BLK       256
#define IPT       16

// Scratch (device globals: no allocation allowed)
__device__ int2 g_runs[M_CAP];   // {start element index, id value} of run s
__device__ int  g_block_cnt[NB];
__device__ int  g_block_pfx[NB]; // exclusive prefix of block counts
__device__ int  g_num_runs;

// ---------------------------------------------------------------------------
// Kernel 1: count run-starts per block. A start is i==0 or ids[i]!=ids[i-1].
// ---------------------------------------------------------------------------
__global__ __launch_bounds__(BLK) void k_count(const int* __restrict__ ids) {
    const int b  = blockIdx.x;
    const int t  = threadIdx.x;
    const int i0 = b * EPB + t * IPT;

    const int4* p = reinterpret_cast<const int4*>(ids + i0);
    int4 a0 = p[0], a1 = p[1], a2 = p[2], a3 = p[3];
    int v[IPT] = {a0.x, a0.y, a0.z, a0.w,
                  a1.x, a1.y, a1.z, a1.w,
                  a2.x, a2.y, a2.z, a2.w,
                  a3.x, a3.y, a3.z, a3.w};

    int prev = (i0 == 0) ? ~v[0] : ids[i0 - 1];
    int cnt = 0;
#pragma unroll
    for (int j = 0; j < IPT; j++) {
        cnt += (v[j] != prev);
        prev = v[j];
    }

    __shared__ int sh[BLK / 32];
#pragma unroll
    for (int off = 16; off > 0; off >>= 1)
        cnt += __shfl_down_sync(0xFFFFFFFFu, cnt, off);
    if ((t & 31) == 0) sh[t >> 5] = cnt;
    __syncthreads();
    if (t < BLK / 32) {
        int s = sh[t];
#pragma unroll
        for (int off = (BLK / 64); off > 0; off >>= 1)
            s += __shfl_down_sync(0xFFu, s, off);
        if (t == 0) g_block_cnt[b] = s;
    }
}

// ---------------------------------------------------------------------------
// Kernel 2: single-block exclusive scan of NB block counts (shuffle-based).
// ---------------------------------------------------------------------------
__global__ __launch_bounds__(NB) void k_scan() {
    const int t    = threadIdx.x;
    const int lane = t & 31;
    const int wid  = t >> 5;
    const int v = g_block_cnt[t];

    int s = v;                                    // inclusive warp scan
#pragma unroll
    for (int off = 1; off < 32; off <<= 1) {
        int x = __shfl_up_sync(0xFFFFFFFFu, s, off);
        if (lane >= off) s += x;
    }

    __shared__ int ws[32];
    if (lane == 31) ws[wid] = s;
    __syncthreads();
    if (wid == 0) {
        int x = ws[lane];
        int y = x;
#pragma unroll
        for (int off = 1; off < 32; off <<= 1) {
            int z = __shfl_up_sync(0xFFFFFFFFu, y, off);
            if (lane >= off) y += z;
        }
        ws[lane] = y - x;                         // exclusive warp base
    }
    __syncthreads();

    const int incl = s + ws[wid];
    g_block_pfx[t] = incl - v;                    // exclusive
    if (t == NB - 1) g_num_runs = incl;
}

// ---------------------------------------------------------------------------
// Kernel 3: recompute starts, block-local exclusive scan, scatter (start,id).
// ---------------------------------------------------------------------------
__global__ __launch_bounds__(BLK) void k_starts(const int* __restrict__ ids) {
    const int b  = blockIdx.x;
    const int t  = threadIdx.x;
    const int i0 = b * EPB + t * IPT;

    const int4* p = reinterpret_cast<const int4*>(ids + i0);
    int4 a0 = p[0], a1 = p[1], a2 = p[2], a3 = p[3];
    int v[IPT] = {a0.x, a0.y, a0.z, a0.w,
                  a1.x, a1.y, a1.z, a1.w,
                  a2.x, a2.y, a2.z, a2.w,
                  a3.x, a3.y, a3.z, a3.w};

    int first_prev = (i0 == 0) ? ~v[0] : ids[i0 - 1];

    int prev = first_prev;
    int cnt = 0;
#pragma unroll
    for (int j = 0; j < IPT; j++) {
        cnt += (v[j] != prev);
        prev = v[j];
    }

    // block-wide exclusive scan of per-thread counts (shuffle 2-level)
    const int lane = t & 31;
    const int wid  = t >> 5;
    int s = cnt;
#pragma unroll
    for (int off = 1; off < 32; off <<= 1) {
        int x = __shfl_up_sync(0xFFFFFFFFu, s, off);
        if (lane >= off) s += x;
    }
    __shared__ int ws[BLK / 32];
    if (lane == 31) ws[wid] = s;
    __syncthreads();
    if (wid == 0 && lane < BLK / 32) {
        int x = ws[lane];
        int y = x;
#pragma unroll
        for (int off = 1; off < BLK / 32; off <<= 1) {
            int z = __shfl_up_sync(0xFFu, y, off);
            if (lane >= off) y += z;
        }
        ws[lane] = y - x;
    }
    __syncthreads();
    int rank = g_block_pfx[b] + ws[wid] + (s - cnt);

    prev = first_prev;
#pragma unroll
    for (int j = 0; j < IPT; j++) {
        if (v[j] != prev) {
            g_runs[rank] = make_int2(i0 + j, v[j]);
            rank++;
        }
        prev = v[j];
    }
}

// ---------------------------------------------------------------------------
// Kernel 4: one WARP per aligned 128-float output window.
// Flat layout (float32): out[0..M_CAP) = run_ids, then padded [M_CAP x 128].
// Since M_CAP % 128 == 1:
//   - windows 0..2047       : pure run_ids
//   - window  w >= 2048     : col 127 of row A=w-2049, then cols 0..126 of
//                             row B=A+1 (window 2048: A=-1, first float is
//                             run_ids[M_CAP-1], always -1).
// Metadata per warp: g_runs[A].x, g_runs[A+1].x, g_runs[A+2].x (3 words,
// loaded by lanes 0..2, shfl-broadcast). Lane l writes one aligned float4.
// ---------------------------------------------------------------------------
__global__ __launch_bounds__(256) void k_fill(const float* __restrict__ feats,
                                              float* __restrict__ out) {
    if (blockIdx.x == 0 && threadIdx.x == 0)
        out[OUT_TOTAL - 1] = 0.0f;                // tail float (always padding)

    const int warp = blockIdx.x * 8 + (threadIdx.x >> 5);
    const int lane = threadIdx.x & 31;
    if (warp >= NW) return;

    const int nr1 = g_num_runs - 1;               // runs actually emitted
    float4 v;

    if (warp < 2048) {
        // ---- run_ids region ----
        const int e = warp * 128 + lane * 4;
        v.x = (e     < nr1) ? (float)g_runs[e    ].y : -1.0f;
        v.y = (e + 1 < nr1) ? (float)g_runs[e + 1].y : -1.0f;
        v.z = (e + 2 < nr1) ? (float)g_runs[e + 2].y : -1.0f;
        v.w = (e + 3 < nr1) ? (float)g_runs[e + 3].y : -1.0f;
    } else {
        // ---- padded region ----
        const int A = warp - 2049;                // -1 for warp == 2048
        int m = 0;
        if (lane < 3) {
            int idx = A + lane;
            idx = idx < 0 ? 0 : idx;
            idx = idx > nr1 ? nr1 : idx;          // clamp into written region
            m = g_runs[idx].x;
        }
        const int sA = __shfl_sync(0xFFFFFFFFu, m, 0);
        const int sB = __shfl_sync(0xFFFFFFFFu, m, 1);
        const int sC = __shfl_sync(0xFFFFFFFFu, m, 2);
        const bool vA = ((unsigned)A       < (unsigned)nr1);
        const bool vB = ((unsigned)(A + 1) < (unsigned)nr1);
        const int lenA = sB - sA;
        const int lenB = sC - sB;

        if (lane == 0) {
            v.x = (vA && lenA > 127) ? feats[sA + 127]
                                     : (A < 0 ? -1.0f : 0.0f);
            v.y = (vB && 0 < lenB) ? feats[sB    ] : 0.0f;
            v.z = (vB && 1 < lenB) ? feats[sB + 1] : 0.0f;
            v.w = (vB && 2 < lenB) ? feats[sB + 2] : 0.0f;
        } else {
            const int c = 4 * lane - 1;
            v.x = (vB && c     < lenB) ? feats[sB + c    ] : 0.0f;
            v.y = (vB && c + 1 < lenB) ? feats[sB + c + 1] : 0.0f;
            v.z = (vB && c + 2 < lenB) ? feats[sB + c + 2] : 0.0f;
            v.w = (vB && c + 3 < lenB) ? feats[sB + c + 3] : 0.0f;
        }
    }

    // streaming store: output exceeds L2 and is never re-read
    __stcs(reinterpret_cast<float4*>(out) + (size_t)warp * 32 + lane, v);
}

// ---------------------------------------------------------------------------
extern "C" void kernel_launch(void* const* d_in, const int* in_sizes, int n_in,
                              void* d_out, int out_size) {
    const int*   ids   = (const int*)d_in[0];
    const float* feats = (const float*)d_in[1];
    float*       out   = (float*)d_out;

    k_count <<<NB, BLK>>>(ids);
    k_scan  <<<1, NB>>>();
    k_starts<<<NB, BLK>>>(ids);

    const int fill_blocks = (NW + 7) / 8;         // 8 warps per block
    k_fill  <<<fill_blocks, 256>>>(feats, out);
}